// round 2
// baseline (speedup 1.0000x reference)
#include <cuda_runtime.h>
#include <math.h>
#include <stdint.h>

// Problem constants
constexpr int BB  = 4;
constexpr int MM  = 2048;
constexpr int DD  = 1024;
constexpr int HH  = 16;
constexpr int DHD = 64;
constexpr int RRA = 256;   // attn rank
constexpr int FFD = 2048;  // ffn intermediate
constexpr int RR1 = 512;
constexpr int RR2 = 512;
constexpr size_t NROWS = (size_t)BB * MM;   // 8192

// ---------------- scratch (single __device__ buffer, no allocs) -------------
constexpr size_t O_XN  = 0;
constexpr size_t O_PQ  = O_XN  + NROWS * DD;
constexpr size_t O_PK  = O_PQ  + NROWS * RRA;
constexpr size_t O_PV  = O_PK  + NROWS * RRA;
constexpr size_t O_QD  = O_PV  + NROWS * RRA;
constexpr size_t O_KD  = O_QD  + NROWS * DD;
constexpr size_t O_VD  = O_KD  + NROWS * DD;
constexpr size_t O_Q   = O_VD  + NROWS * DD;
constexpr size_t O_K   = O_Q   + NROWS * DD;
constexpr size_t O_V   = O_K   + NROWS * DD;
constexpr size_t O_O   = O_V   + NROWS * DD;
constexpr size_t O_AT  = O_O   + NROWS * DD;
constexpr size_t O_X1  = O_AT  + NROWS * DD;
constexpr size_t O_XN2 = O_X1  + NROWS * DD;
constexpr size_t O_P1  = O_XN2 + NROWS * DD;
constexpr size_t O_H   = O_P1  + NROWS * RR1;
constexpr size_t O_G   = O_H   + NROWS * 2 * FFD;
constexpr size_t O_T   = O_G   + NROWS * FFD;
constexpr size_t TOTAL = O_T   + NROWS * RR2;

__device__ float g_buf[TOTAL];

// ---------------- LayerNorm -------------------------------------------------
__global__ void ln_kernel(const float* __restrict__ x, const float* __restrict__ w,
                          const float* __restrict__ b, float* __restrict__ y)
{
    __shared__ float s1[256], s2[256];
    int row = blockIdx.x;
    const float* xr = x + (size_t)row * DD;
    float a = 0.f, q = 0.f;
    for (int i = threadIdx.x; i < DD; i += 256) { float v = xr[i]; a += v; q += v * v; }
    s1[threadIdx.x] = a; s2[threadIdx.x] = q;
    __syncthreads();
    for (int o = 128; o > 0; o >>= 1) {
        if (threadIdx.x < o) { s1[threadIdx.x] += s1[threadIdx.x + o]; s2[threadIdx.x] += s2[threadIdx.x + o]; }
        __syncthreads();
    }
    float mu  = s1[0] / DD;
    float var = s2[0] / DD - mu * mu;
    float rstd = rsqrtf(var + 1e-5f);
    for (int i = threadIdx.x; i < DD; i += 256)
        y[(size_t)row * DD + i] = (xr[i] - mu) * rstd * w[i] + b[i];
}

// ---------------- 128x128x8 SGEMM, 8x8 microtile ----------------------------
// C[M,N] = A[M,K] @ B(K,N)   (or B[N,K] if TRANSB)  (+bias per col) (+res)
// Requires M%128==0, N%128==0, K%8==0.
template<bool TRANSB, bool BIAS, bool RES>
__global__ void __launch_bounds__(256, 2)
sgemm_kernel(const float* __restrict__ A, const float* __restrict__ Bm,
             const float* __restrict__ bias, const float* __restrict__ res,
             float* __restrict__ C, int Mn, int Nn, int Kn)
{
    __shared__ __align__(16) float As[8][132];
    __shared__ __align__(16) float Bs[8][132];
    int tid = threadIdx.x;
    int tx = tid & 15, ty = tid >> 4;
    int mb = blockIdx.y * 128, nb = blockIdx.x * 128;

    float acc[8][8];
#pragma unroll
    for (int i = 0; i < 8; i++)
#pragma unroll
        for (int j = 0; j < 8; j++) acc[i][j] = 0.f;

    for (int k0 = 0; k0 < Kn; k0 += 8) {
        // A tile: 128 rows x 8 K. Each thread: one float4.
        {
            int r = tid >> 1, c = (tid & 1) * 4;
            float4 a4 = *(const float4*)&A[(size_t)(mb + r) * Kn + k0 + c];
            As[c + 0][r] = a4.x; As[c + 1][r] = a4.y;
            As[c + 2][r] = a4.z; As[c + 3][r] = a4.w;
        }
        if (!TRANSB) {
            int r = tid >> 5, c = (tid & 31) * 4;
            float4 b4 = *(const float4*)&Bm[(size_t)(k0 + r) * Nn + nb + c];
            *(float4*)&Bs[r][c] = b4;
        } else {
            int r = tid >> 1, c = (tid & 1) * 4;  // r over N rows, c over K
            float4 b4 = *(const float4*)&Bm[(size_t)(nb + r) * Kn + k0 + c];
            Bs[c + 0][r] = b4.x; Bs[c + 1][r] = b4.y;
            Bs[c + 2][r] = b4.z; Bs[c + 3][r] = b4.w;
        }
        __syncthreads();
#pragma unroll
        for (int k = 0; k < 8; k++) {
            float a[8], b[8];
            *(float4*)&a[0] = *(float4*)&As[k][ty * 4];
            *(float4*)&a[4] = *(float4*)&As[k][64 + ty * 4];
            *(float4*)&b[0] = *(float4*)&Bs[k][tx * 4];
            *(float4*)&b[4] = *(float4*)&Bs[k][64 + tx * 4];
#pragma unroll
            for (int i = 0; i < 8; i++)
#pragma unroll
                for (int j = 0; j < 8; j++)
                    acc[i][j] += a[i] * b[j];
        }
        __syncthreads();
    }

#pragma unroll
    for (int i = 0; i < 8; i++) {
        int row = mb + (i < 4 ? ty * 4 + i : 64 + ty * 4 + (i - 4));
#pragma unroll
        for (int j = 0; j < 8; j++) {
            int col = nb + (j < 4 ? tx * 4 + j : 64 + tx * 4 + (j - 4));
            float v = acc[i][j];
            if (BIAS) v += bias[col];
            if (RES)  v += res[(size_t)row * Nn + col];
            C[(size_t)row * Nn + col] = v;
        }
    }
}

// ---------------- RoPE + [B,M,H*dh] -> [B,H,M,dh] permute -------------------
__global__ void rope_permute_kernel(const float* __restrict__ src, float* __restrict__ dst,
                                    int do_rope)
{
    int idx = blockIdx.x * blockDim.x + threadIdx.x;     // over B*H*M*32
    if (idx >= BB * HH * MM * 32) return;
    int d = idx & 31;
    int t = idx >> 5;
    int m = t % MM; t /= MM;
    int h = t % HH; int b = t / HH;
    size_t sb = ((size_t)(b * MM + m)) * DD + h * DHD;
    float x1 = src[sb + d];
    float x2 = src[sb + d + 32];
    size_t db = (((size_t)(b * HH + h)) * MM + m) * DHD;
    if (do_rope) {
        float inv = powf(10000.0f, -(float)(2 * d) / 64.0f);
        float ang = (float)m * inv;
        float c = cosf(ang), s = sinf(ang);
        dst[db + d]      = x1 * c - x2 * s;
        dst[db + d + 32] = x2 * c + x1 * s;
    } else {
        dst[db + d]      = x1;
        dst[db + d + 32] = x2;
    }
}

// ---------------- flash attention (fp32, 64x64 tiles) -----------------------
__global__ void attn_kernel(const float* __restrict__ Q, const float* __restrict__ K,
                            const float* __restrict__ V, const int* __restrict__ mask,
                            float* __restrict__ O)
{
    extern __shared__ float sm[];
    float* Qs = sm;                 // 64*68
    float* Ks = Qs + 64 * 68;
    float* Vs = Ks + 64 * 68;
    float* Ps = Vs + 64 * 68;
    int*   Mk = (int*)(Ps + 64 * 68);   // 64 ints

    int bh = blockIdx.y;
    int b  = bh / HH;
    int qb = blockIdx.x * 64;
    const float* Qp = Q + (size_t)bh * MM * DHD;
    const float* Kp = K + (size_t)bh * MM * DHD;
    const float* Vp = V + (size_t)bh * MM * DHD;
    int tid = threadIdx.x;
    int tx = tid & 15, ty = tid >> 4;

    for (int i = tid; i < 64 * 16; i += 256) {
        int r = i >> 4, c4 = (i & 15) << 2;
        *(float4*)&Qs[r * 68 + c4] = *(const float4*)&Qp[(size_t)(qb + r) * DHD + c4];
    }

    float mi[4], li[4], o[4][4];
#pragma unroll
    for (int i = 0; i < 4; i++) {
        mi[i] = -1e30f; li[i] = 0.f;
#pragma unroll
        for (int j = 0; j < 4; j++) o[i][j] = 0.f;
    }

    for (int kb = 0; kb < MM; kb += 64) {
        __syncthreads();
        for (int i = tid; i < 64 * 16; i += 256) {
            int r = i >> 4, c4 = (i & 15) << 2;
            *(float4*)&Ks[r * 68 + c4] = *(const float4*)&Kp[(size_t)(kb + r) * DHD + c4];
            *(float4*)&Vs[r * 68 + c4] = *(const float4*)&Vp[(size_t)(kb + r) * DHD + c4];
        }
        if (tid < 64) Mk[tid] = mask[b * MM + kb + tid];
        __syncthreads();

        float s[4][4];
#pragma unroll
        for (int i = 0; i < 4; i++)
#pragma unroll
            for (int j = 0; j < 4; j++) s[i][j] = 0.f;

        for (int d = 0; d < 64; d += 4) {
            float4 q4[4], k4[4];
#pragma unroll
            for (int i = 0; i < 4; i++) q4[i] = *(float4*)&Qs[(4 * ty + i) * 68 + d];
#pragma unroll
            for (int j = 0; j < 4; j++) k4[j] = *(float4*)&Ks[(4 * tx + j) * 68 + d];
#pragma unroll
            for (int i = 0; i < 4; i++)
#pragma unroll
                for (int j = 0; j < 4; j++)
                    s[i][j] += q4[i].x * k4[j].x + q4[i].y * k4[j].y
                             + q4[i].z * k4[j].z + q4[i].w * k4[j].w;
        }

        const float sc = 0.125f;  // 1/sqrt(64)
#pragma unroll
        for (int i = 0; i < 4; i++)
#pragma unroll
            for (int j = 0; j < 4; j++) {
                float v = s[i][j] * sc;
                if (Mk[4 * tx + j] == 0) v = -1e30f;
                s[i][j] = v;
            }

#pragma unroll
        for (int i = 0; i < 4; i++) {
            float rm = fmaxf(fmaxf(s[i][0], s[i][1]), fmaxf(s[i][2], s[i][3]));
#pragma unroll
            for (int ofs = 8; ofs > 0; ofs >>= 1)
                rm = fmaxf(rm, __shfl_xor_sync(0xffffffffu, rm, ofs));
            float mnew = fmaxf(mi[i], rm);
            float corr = expf(mi[i] - mnew);
            float rs = 0.f;
#pragma unroll
            for (int j = 0; j < 4; j++) { float p = expf(s[i][j] - mnew); s[i][j] = p; rs += p; }
#pragma unroll
            for (int ofs = 8; ofs > 0; ofs >>= 1)
                rs += __shfl_xor_sync(0xffffffffu, rs, ofs);
            li[i] = li[i] * corr + rs;
            mi[i] = mnew;
#pragma unroll
            for (int j = 0; j < 4; j++) o[i][j] *= corr;
#pragma unroll
            for (int j = 0; j < 4; j++) Ps[(4 * ty + i) * 68 + 4 * tx + j] = s[i][j];
        }
        __syncthreads();

        for (int k = 0; k < 64; k += 4) {
            float4 p4[4], v4[4];
#pragma unroll
            for (int i = 0; i < 4; i++)  p4[i]  = *(float4*)&Ps[(4 * ty + i) * 68 + k];
#pragma unroll
            for (int kk = 0; kk < 4; kk++) v4[kk] = *(float4*)&Vs[(k + kk) * 68 + 4 * tx];
#pragma unroll
            for (int i = 0; i < 4; i++) {
                o[i][0] += p4[i].x * v4[0].x + p4[i].y * v4[1].x + p4[i].z * v4[2].x + p4[i].w * v4[3].x;
                o[i][1] += p4[i].x * v4[0].y + p4[i].y * v4[1].y + p4[i].z * v4[2].y + p4[i].w * v4[3].y;
                o[i][2] += p4[i].x * v4[0].z + p4[i].y * v4[1].z + p4[i].z * v4[2].z + p4[i].w * v4[3].z;
                o[i][3] += p4[i].x * v4[0].w + p4[i].y * v4[1].w + p4[i].z * v4[2].w + p4[i].w * v4[3].w;
            }
        }
    }

#pragma unroll
    for (int i = 0; i < 4; i++) {
        float inv = 1.f / li[i];
#pragma unroll
        for (int j = 0; j < 4; j++)
            O[((size_t)bh * MM + qb + 4 * ty + i) * DHD + 4 * tx + j] = o[i][j] * inv;
    }
}

// ---------------- [B,H,M,dh] -> [B,M,H*dh] ----------------------------------
__global__ void unpermute_kernel(const float* __restrict__ O, float* __restrict__ out)
{
    size_t idx = (size_t)blockIdx.x * blockDim.x + threadIdx.x;
    if (idx >= NROWS * DD) return;
    int col = (int)(idx % DD);
    int row = (int)(idx / DD);
    int b = row / MM, m = row % MM;
    int h = col / DHD, d = col % DHD;
    out[idx] = O[(((size_t)(b * HH + h)) * MM + m) * DHD + d];
}

// ---------------- GEGLU ------------------------------------------------------
__global__ void geglu_kernel(const float* __restrict__ h, float* __restrict__ g)
{
    size_t i = (size_t)blockIdx.x * blockDim.x + threadIdx.x;
    if (i >= NROWS * FFD) return;
    size_t r = i / FFD, c = i % FFD;
    float a  = h[r * 2 * FFD + c];
    float bv = h[r * 2 * FFD + FFD + c];
    float t  = 0.7978845608028654f * (a + 0.044715f * a * a * a);
    float gl = 0.5f * a * (1.0f + tanhf(t));
    g[i] = gl * bv;
}

// ---------------- launch ------------------------------------------------------
extern "C" void kernel_launch(void* const* d_in, const int* in_sizes, int n_in,
                              void* d_out, int out_size)
{
    const float* x    = (const float*)d_in[0];
    const int*   am   = (const int*)  d_in[1];
    const float* ln1w = (const float*)d_in[2];
    const float* ln1b = (const float*)d_in[3];
    const float* ln2w = (const float*)d_in[4];
    const float* ln2b = (const float*)d_in[5];
    const float* Uq   = (const float*)d_in[6];
    const float* Uk   = (const float*)d_in[7];
    const float* Uv   = (const float*)d_in[8];
    const float* Vq   = (const float*)d_in[9];
    const float* Vk   = (const float*)d_in[10];
    const float* Vv   = (const float*)d_in[11];
    const float* bq   = (const float*)d_in[12];
    const float* bk   = (const float*)d_in[13];
    const float* bv   = (const float*)d_in[14];
    const float* Wo   = (const float*)d_in[15];
    const float* Wob  = (const float*)d_in[16];
    const float* U1   = (const float*)d_in[17];
    const float* V1   = (const float*)d_in[18];
    const float* b1   = (const float*)d_in[19];
    const float* U2   = (const float*)d_in[20];
    const float* V2   = (const float*)d_in[21];
    const float* b2   = (const float*)d_in[22];
    float* out = (float*)d_out;

    float* base = nullptr;
    cudaGetSymbolAddress((void**)&base, g_buf);
    float* xn  = base + O_XN;
    float* Pq  = base + O_PQ;
    float* Pk  = base + O_PK;
    float* Pv  = base + O_PV;
    float* Qd  = base + O_QD;
    float* Kd  = base + O_KD;
    float* Vd  = base + O_VD;
    float* Qb  = base + O_Q;
    float* Kb  = base + O_K;
    float* Vb  = base + O_V;
    float* Ob  = base + O_O;
    float* at  = base + O_AT;
    float* x1  = base + O_X1;
    float* xn2 = base + O_XN2;
    float* P1  = base + O_P1;
    float* Hb  = base + O_H;
    float* Gb  = base + O_G;
    float* Tb  = base + O_T;

    const int ROWS = (int)NROWS;

    // 1. LN1
    ln_kernel<<<ROWS, 256>>>(x, ln1w, ln1b, xn);

    // 2. rank projections (xn @ U*)
    sgemm_kernel<false,false,false><<<dim3(RRA/128, ROWS/128), 256>>>(xn, Uq, nullptr, nullptr, Pq, ROWS, RRA, DD);
    sgemm_kernel<false,false,false><<<dim3(RRA/128, ROWS/128), 256>>>(xn, Uk, nullptr, nullptr, Pk, ROWS, RRA, DD);
    sgemm_kernel<false,false,false><<<dim3(RRA/128, ROWS/128), 256>>>(xn, Uv, nullptr, nullptr, Pv, ROWS, RRA, DD);

    // 3. expand (P* @ V* + b*)
    sgemm_kernel<false,true,false><<<dim3(DD/128, ROWS/128), 256>>>(Pq, Vq, bq, nullptr, Qd, ROWS, DD, RRA);
    sgemm_kernel<false,true,false><<<dim3(DD/128, ROWS/128), 256>>>(Pk, Vk, bk, nullptr, Kd, ROWS, DD, RRA);
    sgemm_kernel<false,true,false><<<dim3(DD/128, ROWS/128), 256>>>(Pv, Vv, bv, nullptr, Vd, ROWS, DD, RRA);

    // 4. RoPE + permute to [B,H,M,dh]
    {
        int n = BB * HH * MM * 32;
        int g = (n + 255) / 256;
        rope_permute_kernel<<<g, 256>>>(Qd, Qb, 1);
        rope_permute_kernel<<<g, 256>>>(Kd, Kb, 1);
        rope_permute_kernel<<<g, 256>>>(Vd, Vb, 0);
    }

    // 5. attention
    {
        size_t smem = 4 * 64 * 68 * sizeof(float) + 64 * sizeof(int);
        cudaFuncSetAttribute(attn_kernel, cudaFuncAttributeMaxDynamicSharedMemorySize, (int)smem);
        attn_kernel<<<dim3(MM/64, BB*HH), 256, smem>>>(Qb, Kb, Vb, am, Ob);
    }

    // 6. unpermute
    {
        size_t n = NROWS * DD;
        unpermute_kernel<<<(int)((n + 255) / 256), 256>>>(Ob, at);
    }

    // 7. Wo (transposed) + bias + residual
    sgemm_kernel<true,true,true><<<dim3(DD/128, ROWS/128), 256>>>(at, Wo, Wob, x, x1, ROWS, DD, DD);

    // 8. LN2
    ln_kernel<<<ROWS, 256>>>(x1, ln2w, ln2b, xn2);

    // 9-10. FFN up
    sgemm_kernel<false,false,false><<<dim3(RR1/128, ROWS/128), 256>>>(xn2, U1, nullptr, nullptr, P1, ROWS, RR1, DD);
    sgemm_kernel<false,true,false><<<dim3((2*FFD)/128, ROWS/128), 256>>>(P1, V1, b1, nullptr, Hb, ROWS, 2*FFD, RR1);

    // 11. GEGLU
    {
        size_t n = NROWS * FFD;
        geglu_kernel<<<(int)((n + 255) / 256), 256>>>(Hb, Gb);
    }

    // 12-13. FFN down + residual -> out
    sgemm_kernel<false,false,false><<<dim3(RR2/128, ROWS/128), 256>>>(Gb, U2, nullptr, nullptr, Tb, ROWS, RR2, FFD);
    sgemm_kernel<false,true,true><<<dim3(DD/128, ROWS/128), 256>>>(Tb, V2, b2, x1, out, ROWS, DD, RR2);
}

// round 11
// speedup vs baseline: 1.5893x; 1.5893x over previous
#include <cuda_runtime.h>
#include <cuda_bf16.h>
#include <mma.h>
#include <math.h>
#include <stdint.h>

using namespace nvcuda;

// -------------------- problem constants --------------------
constexpr int BB  = 4;
constexpr int MM  = 2048;
constexpr int DD  = 1024;
constexpr int HH  = 16;
constexpr int DHD = 64;
constexpr int RRA = 256;
constexpr int FFD = 2048;
constexpr int RR1 = 512;
constexpr int RR2 = 512;
constexpr size_t NROWS = (size_t)BB * MM;   // 8192

// -------------------- scratch buffers --------------------
// fp32 scratch
constexpr size_t F_QB  = 0;
constexpr size_t F_KB  = F_QB  + NROWS * DD;
constexpr size_t F_VB  = F_KB  + NROWS * DD;
constexpr size_t F_OB  = F_VB  + NROWS * DD;
constexpr size_t F_X1  = F_OB  + NROWS * DD;
constexpr size_t F_H   = F_X1  + NROWS * DD;
constexpr size_t F_TOT = F_H   + NROWS * 2 * FFD;
__device__ float g_fbuf[F_TOT];

// bf16 scratch
constexpr size_t H_WTUQ = 0;
constexpr size_t H_WTUK = H_WTUQ + (size_t)RRA * DD;
constexpr size_t H_WTUV = H_WTUK + (size_t)RRA * DD;
constexpr size_t H_WTVQ = H_WTUV + (size_t)RRA * DD;
constexpr size_t H_WTVK = H_WTVQ + (size_t)DD * RRA;
constexpr size_t H_WTVV = H_WTVK + (size_t)DD * RRA;
constexpr size_t H_WWO  = H_WTVV + (size_t)DD * RRA;
constexpr size_t H_WTU1 = H_WWO  + (size_t)DD * DD;
constexpr size_t H_WTV1 = H_WTU1 + (size_t)RR1 * DD;
constexpr size_t H_WTU2 = H_WTV1 + (size_t)(2 * FFD) * RR1;
constexpr size_t H_WTV2 = H_WTU2 + (size_t)RR2 * FFD;
constexpr size_t H_XN   = H_WTV2 + (size_t)DD * RR2;
constexpr size_t H_PQ   = H_XN   + NROWS * DD;
constexpr size_t H_PK   = H_PQ   + NROWS * RRA;
constexpr size_t H_PV   = H_PK   + NROWS * RRA;
constexpr size_t H_QD   = H_PV   + NROWS * RRA;
constexpr size_t H_KD   = H_QD   + NROWS * DD;
constexpr size_t H_VD   = H_KD   + NROWS * DD;
constexpr size_t H_AT   = H_VD   + NROWS * DD;
constexpr size_t H_XN2  = H_AT   + NROWS * DD;
constexpr size_t H_P1   = H_XN2  + NROWS * DD;
constexpr size_t H_G    = H_P1   + NROWS * RR1;
constexpr size_t H_T    = H_G    + NROWS * FFD;
constexpr size_t H_TOT  = H_T    + NROWS * RR2;
__device__ __nv_bfloat16 g_hbuf[H_TOT];

// -------------------- weight transpose/convert --------------------
// in [Kd, Nd] f32  ->  out [Nd, Kd] bf16
__global__ void w_transpose(const float* __restrict__ in, __nv_bfloat16* __restrict__ out,
                            int Kd, int Nd)
{
    __shared__ float t[32][33];
    int nb = blockIdx.x * 32, kb = blockIdx.y * 32;
    int tx = threadIdx.x, ty = threadIdx.y;  // 32 x 8
#pragma unroll
    for (int i = 0; i < 32; i += 8)
        t[ty + i][tx] = in[(size_t)(kb + ty + i) * Nd + nb + tx];
    __syncthreads();
#pragma unroll
    for (int i = 0; i < 32; i += 8)
        out[(size_t)(nb + ty + i) * Kd + kb + tx] = __float2bfloat16(t[tx][ty + i]);
}

__global__ void w_convert(const float* __restrict__ in, __nv_bfloat16* __restrict__ out, size_t n)
{
    size_t i = (size_t)blockIdx.x * blockDim.x + threadIdx.x;
    if (i < n) out[i] = __float2bfloat16(in[i]);
}

// -------------------- LayerNorm (f32 in, bf16 out) --------------------
__global__ void ln_kernel(const float* __restrict__ x, const float* __restrict__ w,
                          const float* __restrict__ b, __nv_bfloat16* __restrict__ y)
{
    __shared__ float s1[256], s2[256];
    int row = blockIdx.x;
    const float* xr = x + (size_t)row * DD;
    float a = 0.f, q = 0.f;
    for (int i = threadIdx.x; i < DD; i += 256) { float v = xr[i]; a += v; q += v * v; }
    s1[threadIdx.x] = a; s2[threadIdx.x] = q;
    __syncthreads();
    for (int o = 128; o > 0; o >>= 1) {
        if (threadIdx.x < o) { s1[threadIdx.x] += s1[threadIdx.x + o]; s2[threadIdx.x] += s2[threadIdx.x + o]; }
        __syncthreads();
    }
    float mu  = s1[0] / DD;
    float var = s2[0] / DD - mu * mu;
    float rstd = rsqrtf(var + 1e-5f);
    for (int i = threadIdx.x; i < DD; i += 256)
        y[(size_t)row * DD + i] = __float2bfloat16((xr[i] - mu) * rstd * w[i] + b[i]);
}

// -------------------- wmma bf16 GEMM --------------------
// C[Mn,Nn] = A[Mn,Kn](bf16) @ B[Nn,Kn](bf16)^T  (+bias) (+res f32)
// CTA tile 128x128, 8 warps (each 32x64), K-chunk 32, double-buffered smem.
// Requires Mn%128==0, Nn%128==0, Kn%32==0.
constexpr int WM_LD   = 40;                       // smem tile leading dim (bf16 elems)
constexpr int WM_TILE = 128 * WM_LD;              // elems per tile buffer
constexpr int WM_EPLD = 72;                       // epilogue pitch (f32)
constexpr size_t WM_SMEM = 8 * 32 * WM_EPLD * sizeof(float);  // 73728 (> 2*2*WM_TILE*2 = 40960)

template<bool BIAS, bool RES, bool OUTBF>
__global__ void __launch_bounds__(256)
wm_gemm(const __nv_bfloat16* __restrict__ A, const __nv_bfloat16* __restrict__ Bw,
        const float* __restrict__ bias, const float* __restrict__ res,
        void* __restrict__ Cout, int Mn, int Nn, int Kn)
{
    extern __shared__ __align__(32) char smem[];
    __nv_bfloat16* As = (__nv_bfloat16*)smem;                    // [2][128][WM_LD]
    __nv_bfloat16* Bs = As + 2 * WM_TILE;                        // [2][128][WM_LD]
    float*         Es = (float*)smem;                            // epilogue overlay

    int tid = threadIdx.x, wid = tid >> 5, lane = tid & 31;
    int mb = blockIdx.y * 128, nb = blockIdx.x * 128;
    int wr = wid & 3, wc = wid >> 2;    // warp 32-row band, 64-col band

    wmma::fragment<wmma::accumulator, 16, 16, 16, float> acc[2][4];
#pragma unroll
    for (int i = 0; i < 2; i++)
#pragma unroll
        for (int j = 0; j < 4; j++) wmma::fill_fragment(acc[i][j], 0.f);

    const int NCH = Kn >> 5;            // K-chunks of 32
    int lrow = tid >> 1, lhalf = tid & 1;   // loader: 128 rows x 2 halves of 16 bf16

    const __nv_bfloat16* age = A  + (size_t)(mb + lrow) * Kn + lhalf * 16;
    const __nv_bfloat16* bge = Bw + (size_t)(nb + lrow) * Kn + lhalf * 16;
    uint32_t sidx = lrow * WM_LD + lhalf * 16;

    // preload chunk 0 into buffer 0
    {
        *(uint4*)&As[sidx]     = *(const uint4*)(age);
        *(uint4*)&As[sidx + 8] = *(const uint4*)(age + 8);
        *(uint4*)&Bs[sidx]     = *(const uint4*)(bge);
        *(uint4*)&Bs[sidx + 8] = *(const uint4*)(bge + 8);
    }

    for (int i = 0; i < NCH; i++) {
        int cur = i & 1;
        // prefetch next chunk to registers
        uint4 pa0, pa1, pb0, pb1;
        bool pf = (i + 1 < NCH);
        if (pf) {
            const __nv_bfloat16* ap = age + (size_t)(i + 1) * 32;
            const __nv_bfloat16* bp = bge + (size_t)(i + 1) * 32;
            pa0 = *(const uint4*)(ap);     pa1 = *(const uint4*)(ap + 8);
            pb0 = *(const uint4*)(bp);     pb1 = *(const uint4*)(bp + 8);
        }
        __syncthreads();   // current buffer stores (from prev iter / preload) visible

        const __nv_bfloat16* Ab = As + cur * WM_TILE;
        const __nv_bfloat16* Bb = Bs + cur * WM_TILE;
#pragma unroll
        for (int kk = 0; kk < 2; kk++) {
            wmma::fragment<wmma::matrix_a, 16, 16, 16, __nv_bfloat16, wmma::row_major> af[2];
            wmma::fragment<wmma::matrix_b, 16, 16, 16, __nv_bfloat16, wmma::col_major> bf[4];
#pragma unroll
            for (int m = 0; m < 2; m++)
                wmma::load_matrix_sync(af[m], Ab + (wr * 32 + m * 16) * WM_LD + kk * 16, WM_LD);
#pragma unroll
            for (int n = 0; n < 4; n++)
                wmma::load_matrix_sync(bf[n], Bb + (wc * 64 + n * 16) * WM_LD + kk * 16, WM_LD);
#pragma unroll
            for (int m = 0; m < 2; m++)
#pragma unroll
                for (int n = 0; n < 4; n++)
                    wmma::mma_sync(acc[m][n], af[m], bf[n], acc[m][n]);
        }

        if (pf) {
            int nxt = cur ^ 1;
            *(uint4*)&As[nxt * WM_TILE + sidx]     = pa0;
            *(uint4*)&As[nxt * WM_TILE + sidx + 8] = pa1;
            *(uint4*)&Bs[nxt * WM_TILE + sidx]     = pb0;
            *(uint4*)&Bs[nxt * WM_TILE + sidx + 8] = pb1;
        }
    }

    // -------- epilogue: frags -> smem (overlay) -> bias/res -> gmem --------
    __syncthreads();   // all compute done before overlaying tile smem
    float* ep = Es + wid * 32 * WM_EPLD;
#pragma unroll
    for (int m = 0; m < 2; m++)
#pragma unroll
        for (int n = 0; n < 4; n++)
            wmma::store_matrix_sync(ep + m * 16 * WM_EPLD + n * 16, acc[m][n],
                                    WM_EPLD, wmma::mem_row_major);
    __syncwarp();

    int c0 = nb + wc * 64 + lane * 2;
#pragma unroll 4
    for (int r = 0; r < 32; r++) {
        int row = mb + wr * 32 + r;
        float v0 = ep[r * WM_EPLD + lane * 2];
        float v1 = ep[r * WM_EPLD + lane * 2 + 1];
        size_t base = (size_t)row * Nn + c0;
        if (BIAS) { v0 += bias[c0]; v1 += bias[c0 + 1]; }
        if (RES)  { v0 += res[base]; v1 += res[base + 1]; }
        if (OUTBF) {
            *(__nv_bfloat162*)&((__nv_bfloat16*)Cout)[base] = __floats2bfloat162_rn(v0, v1);
        } else {
            float2 o = make_float2(v0, v1);
            *(float2*)&((float*)Cout)[base] = o;
        }
    }
}

// -------------------- RoPE + permute (bf16 in, f32 out) --------------------
__global__ void rope_permute_kernel(const __nv_bfloat16* __restrict__ src,
                                    float* __restrict__ dst, int do_rope)
{
    int idx = blockIdx.x * blockDim.x + threadIdx.x;     // over B*H*M*32
    if (idx >= BB * HH * MM * 32) return;
    int d = idx & 31;
    int t = idx >> 5;
    int m = t % MM; t /= MM;
    int h = t % HH; int b = t / HH;
    size_t sb = ((size_t)(b * MM + m)) * DD + h * DHD;
    float x1 = __bfloat162float(src[sb + d]);
    float x2 = __bfloat162float(src[sb + d + 32]);
    size_t db = (((size_t)(b * HH + h)) * MM + m) * DHD;
    if (do_rope) {
        float inv = powf(10000.0f, -(float)(2 * d) / 64.0f);
        float ang = (float)m * inv;
        float c = cosf(ang), s = sinf(ang);
        dst[db + d]      = x1 * c - x2 * s;
        dst[db + d + 32] = x2 * c + x1 * s;
    } else {
        dst[db + d]      = x1;
        dst[db + d + 32] = x2;
    }
}

// -------------------- flash attention (fp32, 64x64 tiles) --------------------
__global__ void attn_kernel(const float* __restrict__ Q, const float* __restrict__ K,
                            const float* __restrict__ V, const int* __restrict__ mask,
                            float* __restrict__ O)
{
    extern __shared__ float sm[];
    float* Qs = sm;
    float* Ks = Qs + 64 * 68;
    float* Vs = Ks + 64 * 68;
    float* Ps = Vs + 64 * 68;
    int*   Mk = (int*)(Ps + 64 * 68);

    int bh = blockIdx.y;
    int b  = bh / HH;
    int qb = blockIdx.x * 64;
    const float* Qp = Q + (size_t)bh * MM * DHD;
    const float* Kp = K + (size_t)bh * MM * DHD;
    const float* Vp = V + (size_t)bh * MM * DHD;
    int tid = threadIdx.x;
    int tx = tid & 15, ty = tid >> 4;

    for (int i = tid; i < 64 * 16; i += 256) {
        int r = i >> 4, c4 = (i & 15) << 2;
        *(float4*)&Qs[r * 68 + c4] = *(const float4*)&Qp[(size_t)(qb + r) * DHD + c4];
    }

    float mi[4], li[4], o[4][4];
#pragma unroll
    for (int i = 0; i < 4; i++) {
        mi[i] = -1e30f; li[i] = 0.f;
#pragma unroll
        for (int j = 0; j < 4; j++) o[i][j] = 0.f;
    }

    for (int kb = 0; kb < MM; kb += 64) {
        __syncthreads();
        for (int i = tid; i < 64 * 16; i += 256) {
            int r = i >> 4, c4 = (i & 15) << 2;
            *(float4*)&Ks[r * 68 + c4] = *(const float4*)&Kp[(size_t)(kb + r) * DHD + c4];
            *(float4*)&Vs[r * 68 + c4] = *(const float4*)&Vp[(size_t)(kb + r) * DHD + c4];
        }
        if (tid < 64) Mk[tid] = mask[b * MM + kb + tid];
        __syncthreads();

        float s[4][4];
#pragma unroll
        for (int i = 0; i < 4; i++)
#pragma unroll
            for (int j = 0; j < 4; j++) s[i][j] = 0.f;

        for (int d = 0; d < 64; d += 4) {
            float4 q4[4], k4[4];
#pragma unroll
            for (int i = 0; i < 4; i++) q4[i] = *(float4*)&Qs[(4 * ty + i) * 68 + d];
#pragma unroll
            for (int j = 0; j < 4; j++) k4[j] = *(float4*)&Ks[(4 * tx + j) * 68 + d];
#pragma unroll
            for (int i = 0; i < 4; i++)
#pragma unroll
                for (int j = 0; j < 4; j++)
                    s[i][j] += q4[i].x * k4[j].x + q4[i].y * k4[j].y
                             + q4[i].z * k4[j].z + q4[i].w * k4[j].w;
        }

        const float sc = 0.125f;
#pragma unroll
        for (int i = 0; i < 4; i++)
#pragma unroll
            for (int j = 0; j < 4; j++) {
                float v = s[i][j] * sc;
                if (Mk[4 * tx + j] == 0) v = -1e30f;
                s[i][j] = v;
            }

#pragma unroll
        for (int i = 0; i < 4; i++) {
            float rm = fmaxf(fmaxf(s[i][0], s[i][1]), fmaxf(s[i][2], s[i][3]));
#pragma unroll
            for (int ofs = 8; ofs > 0; ofs >>= 1)
                rm = fmaxf(rm, __shfl_xor_sync(0xffffffffu, rm, ofs));
            float mnew = fmaxf(mi[i], rm);
            float corr = expf(mi[i] - mnew);
            float rs = 0.f;
#pragma unroll
            for (int j = 0; j < 4; j++) { float p = expf(s[i][j] - mnew); s[i][j] = p; rs += p; }
#pragma unroll
            for (int ofs = 8; ofs > 0; ofs >>= 1)
                rs += __shfl_xor_sync(0xffffffffu, rs, ofs);
            li[i] = li[i] * corr + rs;
            mi[i] = mnew;
#pragma unroll
            for (int j = 0; j < 4; j++) o[i][j] *= corr;
#pragma unroll
            for (int j = 0; j < 4; j++) Ps[(4 * ty + i) * 68 + 4 * tx + j] = s[i][j];
        }
        __syncthreads();

        for (int k = 0; k < 64; k += 4) {
            float4 p4[4], v4[4];
#pragma unroll
            for (int i = 0; i < 4; i++)  p4[i]  = *(float4*)&Ps[(4 * ty + i) * 68 + k];
#pragma unroll
            for (int kk = 0; kk < 4; kk++) v4[kk] = *(float4*)&Vs[(k + kk) * 68 + 4 * tx];
#pragma unroll
            for (int i = 0; i < 4; i++) {
                o[i][0] += p4[i].x * v4[0].x + p4[i].y * v4[1].x + p4[i].z * v4[2].x + p4[i].w * v4[3].x;
                o[i][1] += p4[i].x * v4[0].y + p4[i].y * v4[1].y + p4[i].z * v4[2].y + p4[i].w * v4[3].y;
                o[i][2] += p4[i].x * v4[0].z + p4[i].y * v4[1].z + p4[i].z * v4[2].z + p4[i].w * v4[3].z;
                o[i][3] += p4[i].x * v4[0].w + p4[i].y * v4[1].w + p4[i].z * v4[2].w + p4[i].w * v4[3].w;
            }
        }
    }

#pragma unroll
    for (int i = 0; i < 4; i++) {
        float inv = 1.f / li[i];
#pragma unroll
        for (int j = 0; j < 4; j++)
            O[((size_t)bh * MM + qb + 4 * ty + i) * DHD + 4 * tx + j] = o[i][j] * inv;
    }
}

// -------------------- [B,H,M,dh] -> [B,M,H*dh] (f32 -> bf16) --------------------
__global__ void unpermute_kernel(const float* __restrict__ O, __nv_bfloat16* __restrict__ out)
{
    size_t idx = (size_t)blockIdx.x * blockDim.x + threadIdx.x;
    if (idx >= NROWS * DD) return;
    int col = (int)(idx % DD);
    int row = (int)(idx / DD);
    int b = row / MM, m = row % MM;
    int h = col / DHD, d = col % DHD;
    out[idx] = __float2bfloat16(O[(((size_t)(b * HH + h)) * MM + m) * DHD + d]);
}

// -------------------- GEGLU (f32 in, bf16 out) --------------------
__global__ void geglu_kernel(const float* __restrict__ h, __nv_bfloat16* __restrict__ g)
{
    size_t i = (size_t)blockIdx.x * blockDim.x + threadIdx.x;
    if (i >= NROWS * FFD) return;
    size_t r = i / FFD, c = i % FFD;
    float a  = h[r * 2 * FFD + c];
    float bv = h[r * 2 * FFD + FFD + c];
    float t  = 0.7978845608028654f * (a + 0.044715f * a * a * a);
    float gl = 0.5f * a * (1.0f + tanhf(t));
    g[i] = __float2bfloat16(gl * bv);
}

// -------------------- launch --------------------
extern "C" void kernel_launch(void* const* d_in, const int* in_sizes, int n_in,
                              void* d_out, int out_size)
{
    const float* x    = (const float*)d_in[0];
    const int*   am   = (const int*)  d_in[1];
    const float* ln1w = (const float*)d_in[2];
    const float* ln1b = (const float*)d_in[3];
    const float* ln2w = (const float*)d_in[4];
    const float* ln2b = (const float*)d_in[5];
    const float* Uq   = (const float*)d_in[6];
    const float* Uk   = (const float*)d_in[7];
    const float* Uv   = (const float*)d_in[8];
    const float* Vq   = (const float*)d_in[9];
    const float* Vk   = (const float*)d_in[10];
    const float* Vv   = (const float*)d_in[11];
    const float* bq   = (const float*)d_in[12];
    const float* bk   = (const float*)d_in[13];
    const float* bv   = (const float*)d_in[14];
    const float* Wo   = (const float*)d_in[15];
    const float* Wob  = (const float*)d_in[16];
    const float* U1   = (const float*)d_in[17];
    const float* V1   = (const float*)d_in[18];
    const float* b1   = (const float*)d_in[19];
    const float* U2   = (const float*)d_in[20];
    const float* V2   = (const float*)d_in[21];
    const float* b2   = (const float*)d_in[22];
    float* out = (float*)d_out;

    float* fb = nullptr;
    cudaGetSymbolAddress((void**)&fb, g_fbuf);
    __nv_bfloat16* hb = nullptr;
    cudaGetSymbolAddress((void**)&hb, g_hbuf);

    float* Qb  = fb + F_QB;
    float* Kb  = fb + F_KB;
    float* Vb  = fb + F_VB;
    float* Ob  = fb + F_OB;
    float* x1  = fb + F_X1;
    float* Hb  = fb + F_H;

    __nv_bfloat16* wtUq = hb + H_WTUQ;
    __nv_bfloat16* wtUk = hb + H_WTUK;
    __nv_bfloat16* wtUv = hb + H_WTUV;
    __nv_bfloat16* wtVq = hb + H_WTVQ;
    __nv_bfloat16* wtVk = hb + H_WTVK;
    __nv_bfloat16* wtVv = hb + H_WTVV;
    __nv_bfloat16* wWo  = hb + H_WWO;
    __nv_bfloat16* wtU1 = hb + H_WTU1;
    __nv_bfloat16* wtV1 = hb + H_WTV1;
    __nv_bfloat16* wtU2 = hb + H_WTU2;
    __nv_bfloat16* wtV2 = hb + H_WTV2;
    __nv_bfloat16* xnb  = hb + H_XN;
    __nv_bfloat16* Pqb  = hb + H_PQ;
    __nv_bfloat16* Pkb  = hb + H_PK;
    __nv_bfloat16* Pvb  = hb + H_PV;
    __nv_bfloat16* Qdb  = hb + H_QD;
    __nv_bfloat16* Kdb  = hb + H_KD;
    __nv_bfloat16* Vdb  = hb + H_VD;
    __nv_bfloat16* atb  = hb + H_AT;
    __nv_bfloat16* xn2b = hb + H_XN2;
    __nv_bfloat16* P1b  = hb + H_P1;
    __nv_bfloat16* Gbb  = hb + H_G;
    __nv_bfloat16* Tbb  = hb + H_T;

    const int ROWS = (int)NROWS;
    dim3 tb(32, 8);

    // opt-in dynamic smem for all wm_gemm instantiations
    cudaFuncSetAttribute(wm_gemm<false,false,true>, cudaFuncAttributeMaxDynamicSharedMemorySize, (int)WM_SMEM);
    cudaFuncSetAttribute(wm_gemm<true,false,true>,  cudaFuncAttributeMaxDynamicSharedMemorySize, (int)WM_SMEM);
    cudaFuncSetAttribute(wm_gemm<true,true,false>,  cudaFuncAttributeMaxDynamicSharedMemorySize, (int)WM_SMEM);
    cudaFuncSetAttribute(wm_gemm<true,false,false>, cudaFuncAttributeMaxDynamicSharedMemorySize, (int)WM_SMEM);

    // 0. weight transpose/convert to bf16 [N,K]
    w_transpose<<<dim3(RRA/32, DD/32), tb>>>(Uq, wtUq, DD, RRA);
    w_transpose<<<dim3(RRA/32, DD/32), tb>>>(Uk, wtUk, DD, RRA);
    w_transpose<<<dim3(RRA/32, DD/32), tb>>>(Uv, wtUv, DD, RRA);
    w_transpose<<<dim3(DD/32, RRA/32), tb>>>(Vq, wtVq, RRA, DD);
    w_transpose<<<dim3(DD/32, RRA/32), tb>>>(Vk, wtVk, RRA, DD);
    w_transpose<<<dim3(DD/32, RRA/32), tb>>>(Vv, wtVv, RRA, DD);
    w_convert<<<(DD*DD + 255)/256, 256>>>(Wo, wWo, (size_t)DD * DD);   // [out,in] already [N,K]
    w_transpose<<<dim3(RR1/32, DD/32), tb>>>(U1, wtU1, DD, RR1);
    w_transpose<<<dim3((2*FFD)/32, RR1/32), tb>>>(V1, wtV1, RR1, 2*FFD);
    w_transpose<<<dim3(RR2/32, FFD/32), tb>>>(U2, wtU2, FFD, RR2);
    w_transpose<<<dim3(DD/32, RR2/32), tb>>>(V2, wtV2, RR2, DD);

    // 1. LN1 -> bf16
    ln_kernel<<<ROWS, 256>>>(x, ln1w, ln1b, xnb);

    // 2. rank projections
    wm_gemm<false,false,true><<<dim3(RRA/128, ROWS/128), 256, WM_SMEM>>>(xnb, wtUq, nullptr, nullptr, Pqb, ROWS, RRA, DD);
    wm_gemm<false,false,true><<<dim3(RRA/128, ROWS/128), 256, WM_SMEM>>>(xnb, wtUk, nullptr, nullptr, Pkb, ROWS, RRA, DD);
    wm_gemm<false,false,true><<<dim3(RRA/128, ROWS/128), 256, WM_SMEM>>>(xnb, wtUv, nullptr, nullptr, Pvb, ROWS, RRA, DD);

    // 3. expand
    wm_gemm<true,false,true><<<dim3(DD/128, ROWS/128), 256, WM_SMEM>>>(Pqb, wtVq, bq, nullptr, Qdb, ROWS, DD, RRA);
    wm_gemm<true,false,true><<<dim3(DD/128, ROWS/128), 256, WM_SMEM>>>(Pkb, wtVk, bk, nullptr, Kdb, ROWS, DD, RRA);
    wm_gemm<true,false,true><<<dim3(DD/128, ROWS/128), 256, WM_SMEM>>>(Pvb, wtVv, bv, nullptr, Vdb, ROWS, DD, RRA);

    // 4. RoPE + permute
    {
        int n = BB * HH * MM * 32;
        int g = (n + 255) / 256;
        rope_permute_kernel<<<g, 256>>>(Qdb, Qb, 1);
        rope_permute_kernel<<<g, 256>>>(Kdb, Kb, 1);
        rope_permute_kernel<<<g, 256>>>(Vdb, Vb, 0);
    }

    // 5. attention
    {
        size_t smem = 4 * 64 * 68 * sizeof(float) + 64 * sizeof(int);
        cudaFuncSetAttribute(attn_kernel, cudaFuncAttributeMaxDynamicSharedMemorySize, (int)smem);
        attn_kernel<<<dim3(MM/64, BB*HH), 256, smem>>>(Qb, Kb, Vb, am, Ob);
    }

    // 6. unpermute -> bf16
    {
        size_t n = NROWS * DD;
        unpermute_kernel<<<(int)((n + 255) / 256), 256>>>(Ob, atb);
    }

    // 7. Wo + bias + residual (f32 out)
    wm_gemm<true,true,false><<<dim3(DD/128, ROWS/128), 256, WM_SMEM>>>(atb, wWo, Wob, x, x1, ROWS, DD, DD);

    // 8. LN2 -> bf16
    ln_kernel<<<ROWS, 256>>>(x1, ln2w, ln2b, xn2b);

    // 9-10. FFN up
    wm_gemm<false,false,true><<<dim3(RR1/128, ROWS/128), 256, WM_SMEM>>>(xn2b, wtU1, nullptr, nullptr, P1b, ROWS, RR1, DD);
    wm_gemm<true,false,false><<<dim3((2*FFD)/128, ROWS/128), 256, WM_SMEM>>>(P1b, wtV1, b1, nullptr, Hb, ROWS, 2*FFD, RR1);

    // 11. GEGLU -> bf16
    {
        size_t n = NROWS * FFD;
        geglu_kernel<<<(int)((n + 255) / 256), 256>>>(Hb, Gbb);
    }

    // 12-13. FFN down + residual
    wm_gemm<false,false,true><<<dim3(RR2/128, ROWS/128), 256, WM_SMEM>>>(Gbb, wtU2, nullptr, nullptr, Tbb, ROWS, RR2, FFD);
    wm_gemm<true,true,false><<<dim3(DD/128, ROWS/128), 256, WM_SMEM>>>(Tbb, wtV2, b2, x1, out, ROWS, DD, RR2);
}